// round 1
// baseline (speedup 1.0000x reference)
#include <cuda_runtime.h>
#include <cuda_bf16.h>
#include <math_constants.h>

#define D        128
#define NODES_MX 40000
#define EDGES_MX 640000

// ---------------- scratch (device globals; no allocations allowed) ----------------
__device__ float g_summed[NODES_MX * D];
__device__ float g_qk[NODES_MX * D];
__device__ float g_wm[NODES_MX * D];
__device__ float g_qb[NODES_MX];
__device__ float g_maxs[NODES_MX];
__device__ float g_sums[NODES_MX];
__device__ float g_scores[EDGES_MX];
__device__ float g_exps[EDGES_MX];
__device__ int   g_counts[NODES_MX];
__device__ int   g_offsets[NODES_MX + 1];
__device__ int   g_cursor[NODES_MX];
__device__ int   g_eids[EDGES_MX];
__device__ float g_Wqk[D * D];   // Wq @ Wk^T
__device__ float g_Wvo[D * D];   // Wv @ Wo
__device__ float g_bqk[D];       // bq @ Wk^T
__device__ float g_wqb[D];       // Wq @ bk
__device__ float g_bvo[D];       // bv @ Wo
__device__ float g_bqb[1];       // bq . bk

// ---------------- helpers ----------------
__device__ __forceinline__ void atomicMaxF(float* addr, float v) {
    if (v >= 0.f) atomicMax((int*)addr, __float_as_int(v));
    else          atomicMin((unsigned int*)addr, __float_as_uint(v));
}

// ---------------- init ----------------
__global__ void k_init(int N) {
    int i = blockIdx.x * blockDim.x + threadIdx.x;
    if (i < N) {
        g_counts[i] = 0;
        g_maxs[i]   = -CUDART_INF_F;
        g_sums[i]   = 0.f;
    }
}

// ---------------- precompute fused weights ----------------
__global__ void k_pre(const float* __restrict__ Wk, const float* __restrict__ bk,
                      const float* __restrict__ Wv, const float* __restrict__ bv,
                      const float* __restrict__ Wq, const float* __restrict__ bq,
                      const float* __restrict__ Wo) {
    int i = blockIdx.x;     // 0..127
    int j = threadIdx.x;    // 0..127
    float a = 0.f, c = 0.f;
#pragma unroll 8
    for (int t = 0; t < D; t++) {
        a = fmaf(Wq[i * D + t], Wk[j * D + t], a);   // (Wq Wk^T)[i][j]
        c = fmaf(Wv[i * D + t], Wo[t * D + j], c);   // (Wv Wo)[i][j]
    }
    g_Wqk[i * D + j] = a;
    g_Wvo[i * D + j] = c;
    if (i == 0) {
        float b1 = 0.f, b2 = 0.f, b3 = 0.f;
#pragma unroll 8
        for (int t = 0; t < D; t++) {
            b1 = fmaf(bq[t], Wk[j * D + t], b1);     // (bq Wk^T)[j]
            b2 = fmaf(Wq[j * D + t], bk[t], b2);     // (Wq bk)[j]
            b3 = fmaf(bv[t], Wo[t * D + j], b3);     // (bv Wo)[j]
        }
        g_bqk[j] = b1; g_wqb[j] = b2; g_bvo[j] = b3;
        if (j == 0) {
            float b = 0.f;
            for (int t = 0; t < D; t++) b = fmaf(bq[t], bk[t], b);
            g_bqb[0] = b;
        }
    }
}

// ---------------- CSR build ----------------
__global__ void k_hist(const int* __restrict__ recv, int E) {
    for (int e = blockIdx.x * blockDim.x + threadIdx.x; e < E; e += gridDim.x * blockDim.x)
        atomicAdd(&g_counts[recv[e]], 1);
}

__global__ void k_scan(int N) {
    __shared__ int sh[1024];
    int tid = threadIdx.x;
    int carry = 0;
    for (int base = 0; base < N; base += 1024) {
        int i = base + tid;
        int x = (i < N) ? g_counts[i] : 0;
        sh[tid] = x;
        __syncthreads();
        for (int off = 1; off < 1024; off <<= 1) {
            int v = (tid >= off) ? sh[tid - off] : 0;
            __syncthreads();
            sh[tid] += v;
            __syncthreads();
        }
        int excl = sh[tid] - x;
        if (i < N) { g_offsets[i] = carry + excl; g_cursor[i] = carry + excl; }
        int tot = sh[1023];
        __syncthreads();
        carry += tot;
    }
    if (tid == 0) g_offsets[N] = carry;
}

__global__ void k_scatter(const int* __restrict__ recv, int E) {
    for (int e = blockIdx.x * blockDim.x + threadIdx.x; e < E; e += gridDim.x * blockDim.x) {
        int pos = atomicAdd(&g_cursor[recv[e]], 1);
        g_eids[pos] = e;
    }
}

// ---------------- pass 1: summed[n] = sum of messages over node's edges ----------------
__global__ void k_sum_nodes(const float* __restrict__ messages, int N) {
    int gw = (blockIdx.x * blockDim.x + threadIdx.x) >> 5;
    int lane = threadIdx.x & 31;
    if (gw >= N) return;
    int beg = g_offsets[gw], end = g_offsets[gw + 1];
    const float4* m4 = (const float4*)messages;
    float4 acc = make_float4(0.f, 0.f, 0.f, 0.f);
    for (int k = beg; k < end; k++) {
        int e = g_eids[k];
        float4 m = __ldg(m4 + (size_t)e * 32 + lane);
        acc.x += m.x; acc.y += m.y; acc.z += m.z; acc.w += m.w;
    }
    ((float4*)g_summed)[(size_t)gw * 32 + lane] = acc;
}

// ---------------- node projection: qk = summed @ Wqk + bqk ; qb = summed.wqb + bqb ----
__global__ void k_qkproj(int N) {
    const int TN = 16;
    __shared__ __align__(16) float ss[TN][D];
    int n0 = blockIdx.x * TN;
    int j = threadIdx.x;   // 0..127
#pragma unroll
    for (int u = 0; u < TN; u++) {
        int n = n0 + u; if (n >= N) n = N - 1;
        ss[u][j] = g_summed[(size_t)n * D + j];
    }
    __syncthreads();
    float acc[TN];
    float b = g_bqk[j];
#pragma unroll
    for (int u = 0; u < TN; u++) acc[u] = b;
    for (int i4 = 0; i4 < D / 4; i4++) {
        float w0 = g_Wqk[(4 * i4 + 0) * D + j];
        float w1 = g_Wqk[(4 * i4 + 1) * D + j];
        float w2 = g_Wqk[(4 * i4 + 2) * D + j];
        float w3 = g_Wqk[(4 * i4 + 3) * D + j];
#pragma unroll
        for (int u = 0; u < TN; u++) {
            float4 sv = ((const float4*)ss[u])[i4];
            acc[u] = fmaf(sv.x, w0, acc[u]);
            acc[u] = fmaf(sv.y, w1, acc[u]);
            acc[u] = fmaf(sv.z, w2, acc[u]);
            acc[u] = fmaf(sv.w, w3, acc[u]);
        }
    }
#pragma unroll
    for (int u = 0; u < TN; u++)
        if (n0 + u < N) g_qk[(size_t)(n0 + u) * D + j] = acc[u];
    if (j < TN && n0 + j < N) {
        float a = g_bqb[0];
        for (int i = 0; i < D; i++) a = fmaf(ss[j][i], g_wqb[i], a);
        g_qb[n0 + j] = a;
    }
}

// ---------------- pass 2: per-edge score + segment max ----------------
__global__ void k_scores(const float* __restrict__ messages,
                         const int* __restrict__ recv, int E) {
    int gw = (blockIdx.x * blockDim.x + threadIdx.x) >> 5;
    int lane = threadIdx.x & 31;
    if (gw >= E) return;
    int r = __ldg(recv + gw);
    float4 m = __ldg((const float4*)messages + (size_t)gw * 32 + lane);
    float4 q = __ldg((const float4*)g_qk + (size_t)r * 32 + lane);
    float d = m.x * q.x + m.y * q.y + m.z * q.z + m.w * q.w;
#pragma unroll
    for (int off = 16; off > 0; off >>= 1)
        d += __shfl_xor_sync(0xffffffffu, d, off);
    if (lane == 0) {
        float s = (d + g_qb[r]) * 0.08838834764831845f;   // 1/sqrt(128)
        g_scores[gw] = s;
        atomicMaxF(&g_maxs[r], s);
    }
}

// ---------------- pass 3: exp + segment sum ----------------
__global__ void k_exp(const int* __restrict__ recv, int E) {
    int e = blockIdx.x * blockDim.x + threadIdx.x;
    if (e >= E) return;
    int r = recv[e];
    float es = __expf(g_scores[e] - g_maxs[r]);
    g_exps[e] = es;
    atomicAdd(&g_sums[r], es);
}

// ---------------- pass 4: weighted message aggregation per node ----------------
__global__ void k_agg(const float* __restrict__ messages, int N) {
    int gw = (blockIdx.x * blockDim.x + threadIdx.x) >> 5;
    int lane = threadIdx.x & 31;
    if (gw >= N) return;
    int beg = g_offsets[gw], end = g_offsets[gw + 1];
    float inv = 1.f / (g_sums[gw] + 1e-8f);
    const float4* m4 = (const float4*)messages;
    float4 acc = make_float4(0.f, 0.f, 0.f, 0.f);
    for (int k = beg; k < end; k++) {
        int e = g_eids[k];
        float w = __ldg(&g_exps[e]) * inv;
        float4 m = __ldg(m4 + (size_t)e * 32 + lane);
        acc.x = fmaf(w, m.x, acc.x); acc.y = fmaf(w, m.y, acc.y);
        acc.z = fmaf(w, m.z, acc.z); acc.w = fmaf(w, m.w, acc.w);
    }
    ((float4*)g_wm)[(size_t)gw * 32 + lane] = acc;
}

// ---------------- output projection: out = wm @ Wvo + asum*bvo + bo ----------------
__global__ void k_out(const float* __restrict__ bo, float* __restrict__ out, int N) {
    const int TN = 16;
    __shared__ __align__(16) float ss[TN][D];
    __shared__ float sas[TN];
    int n0 = blockIdx.x * TN;
    int j = threadIdx.x;
#pragma unroll
    for (int u = 0; u < TN; u++) {
        int n = n0 + u; if (n >= N) n = N - 1;
        ss[u][j] = g_wm[(size_t)n * D + j];
    }
    if (j < TN) {
        int n = n0 + j; if (n >= N) n = N - 1;
        float s = g_sums[n];
        sas[j] = s / (s + 1e-8f);
    }
    __syncthreads();
    float bvoj = g_bvo[j];
    float boj  = __ldg(bo + j);
    float acc[TN];
#pragma unroll
    for (int u = 0; u < TN; u++) acc[u] = fmaf(sas[u], bvoj, boj);
    for (int i4 = 0; i4 < D / 4; i4++) {
        float w0 = g_Wvo[(4 * i4 + 0) * D + j];
        float w1 = g_Wvo[(4 * i4 + 1) * D + j];
        float w2 = g_Wvo[(4 * i4 + 2) * D + j];
        float w3 = g_Wvo[(4 * i4 + 3) * D + j];
#pragma unroll
        for (int u = 0; u < TN; u++) {
            float4 sv = ((const float4*)ss[u])[i4];
            acc[u] = fmaf(sv.x, w0, acc[u]);
            acc[u] = fmaf(sv.y, w1, acc[u]);
            acc[u] = fmaf(sv.z, w2, acc[u]);
            acc[u] = fmaf(sv.w, w3, acc[u]);
        }
    }
#pragma unroll
    for (int u = 0; u < TN; u++)
        if (n0 + u < N) out[(size_t)(n0 + u) * D + j] = acc[u];
}

// ---------------- launch ----------------
extern "C" void kernel_launch(void* const* d_in, const int* in_sizes, int n_in,
                              void* d_out, int out_size) {
    const float* messages = (const float*)d_in[0];
    const int*   recv     = (const int*)d_in[1];
    // weights start after optional scalar num_segments input
    int wb = (n_in >= 11) ? 3 : 2;
    const float* Wk = (const float*)d_in[wb + 0];
    const float* bk = (const float*)d_in[wb + 1];
    const float* Wv = (const float*)d_in[wb + 2];
    const float* bv = (const float*)d_in[wb + 3];
    const float* Wq = (const float*)d_in[wb + 4];
    const float* bq = (const float*)d_in[wb + 5];
    const float* Wo = (const float*)d_in[wb + 6];
    const float* bo = (const float*)d_in[wb + 7];
    float* out = (float*)d_out;

    int E = in_sizes[0] / D;
    int N = out_size / D;

    k_init<<<(N + 255) / 256, 256>>>(N);
    k_pre<<<D, D>>>(Wk, bk, Wv, bv, Wq, bq, Wo);
    k_hist<<<(E + 255) / 256, 256>>>(recv, E);
    k_scan<<<1, 1024>>>(N);
    k_scatter<<<(E + 255) / 256, 256>>>(recv, E);
    k_sum_nodes<<<(N * 32 + 255) / 256, 256>>>(messages, N);
    k_qkproj<<<(N + 15) / 16, 128>>>(N);
    k_scores<<<(int)(((long long)E * 32 + 255) / 256), 256>>>(messages, recv, E);
    k_exp<<<(E + 255) / 256, 256>>>(recv, E);
    k_agg<<<(N * 32 + 255) / 256, 256>>>(messages, N);
    k_out<<<(N + 15) / 16, 128>>>(bo, out, N);
}